// round 6
// baseline (speedup 1.0000x reference)
#include <cuda_runtime.h>
#include <cuda_bf16.h>
#include <math.h>

// ---------------------------------------------------------------------------
// Handwriting synthesis network (Graves attention, 3x LSTM-512, GMM head)
// B=64 T=800 U=100 V=80 H=512 KA=10 KO=20
// Persistent scans (256 thr, 2 warps/SMSP) + f32x2 math + flag-array barrier.
// ---------------------------------------------------------------------------

#define Bn   64
#define Tn   800
#define Un   100
#define Vn   80
#define Hn   512
#define KAn  10
#define Gn   2048          // 4*H
#define K1   595           // 3+V+H
#define K1P  608           // padded
#define FCK  1536          // 3*H
#define OUTC 121

// -------------------- f32x2 helpers -----------------------------------------
__device__ __forceinline__ unsigned long long pack2(float x, float y)
{
    unsigned long long r;
    asm("mov.b64 %0, {%1, %2};" : "=l"(r) : "f"(x), "f"(y));
    return r;
}
__device__ __forceinline__ void fma2(unsigned long long& d,
                                     unsigned long long a, unsigned long long b)
{
    asm("fma.rn.f32x2 %0, %1, %2, %0;" : "+l"(d) : "l"(a), "l"(b));
}
__device__ __forceinline__ float2 unpk(unsigned long long v)
{
    float2 f;
    asm("mov.b64 {%0, %1}, %2;" : "=f"(f.x), "=f"(f.y) : "l"(v));
    return f;
}

// -------------------- static device scratch --------------------------------
__device__ float g_h0[(size_t)Tn*Bn*Hn];
__device__ float g_h1[(size_t)Tn*Bn*Hn];
__device__ float g_h2[(size_t)Tn*Bn*Hn];
__device__ float g_w [(size_t)Tn*Bn*Vn];
__device__ float g_kap[Bn*KAn];
// packed weight layouts: [k][ht(64)][u(8)][g(4)]
__device__ float g_Whp0[(size_t)Hn*Gn];
__device__ float g_Whp1[(size_t)Hn*Gn];
__device__ float g_Whp2[(size_t)Hn*Gn];
__device__ float g_Wxp0[(size_t)96*Gn];
__device__ float g_cat[(size_t)Tn*Bn*K1P];
__device__ float g_pre[(size_t)Tn*Bn*Gn];      // layout [n][unit(512)][gate(4)]
__device__ float g_fcraw[(size_t)Tn*Bn*OUTC];

// flag-array barrier: 2 groups x 64 blocks, one 128B line per flag
__device__ unsigned g_flag[2*64*32];

__device__ __forceinline__ float sigf(float x) { return 1.f/(1.f+expf(-x)); }

// 64-block grid barrier per group: each block releases its own epoch flag,
// 64 threads poll the 64 flags in parallel with acquire loads.
__device__ __forceinline__ void grid_bar(int grp, int myht, unsigned ep)
{
    __syncthreads();
    const int tid = threadIdx.x;
    if (tid == 0) {
        unsigned* f = &g_flag[(grp*64 + myht)*32];
        asm volatile("st.release.gpu.u32 [%0], %1;" :: "l"(f), "r"(ep) : "memory");
    }
    if (tid < 64) {
        unsigned* f = &g_flag[(grp*64 + tid)*32];
        unsigned v;
        do {
            asm volatile("ld.acquire.gpu.u32 %0, [%1];" : "=r"(v) : "l"(f) : "memory");
        } while (v < ep);
    }
    __syncthreads();
}

// -------------------- prep kernels ------------------------------------------
// out idx = k*2048 + ht*32 + u*4 + g ; src W[(g*512 + ht*8 + u)*512 + k]
__global__ void k_prep_whh(const float* __restrict__ W, int layer)
{
    int idx = blockIdx.x * 256 + threadIdx.x;
    if (idx >= Hn*Gn) return;
    int g  = idx & 3;
    int u  = (idx >> 2) & 7;
    int ht = (idx >> 5) & 63;
    int k  = idx >> 11;
    float v = W[(size_t)(g*Hn + ht*8 + u)*Hn + k];
    if (layer == 0)      g_Whp0[idx] = v;
    else if (layer == 1) g_Whp1[idx] = v;
    else                 g_Whp2[idx] = v;
}

__global__ void k_prep_wx0(const float* __restrict__ Wih0)
{
    int idx = blockIdx.x * 256 + threadIdx.x;
    if (idx < 2*64*32) g_flag[idx] = 0;        // reset barrier flags each run
    if (idx >= 96*Gn) return;
    int g  = idx & 3;
    int u  = (idx >> 2) & 7;
    int ht = (idx >> 5) & 63;
    int k  = idx >> 11;
    g_Wxp0[idx] = (k < 83) ? Wih0[(size_t)(g*Hn + ht*8 + u)*83 + k] : 0.f;
}

// -------------------- persistent scan shapes ---------------------------------
// grid 128 = (bt 0..1)*64 + (ht 0..63). block 256 threads.
// thread: u = tid&7 (unit within 8), bl = tid>>3 (batch within 32).
#define WS_F   (512*32)
#define WS0_F  (96*32)
#define XS_F   (32*100)
#define HS_F   (32*516)

__device__ __forceinline__ void attn_step(
    int t, int b, const float* __restrict__ W_att, const float* __restrict__ b_att,
    const int* __restrict__ chars, const float* __restrict__ cmask, float* sc)
{
    float* red = sc;          // 256
    float* abk = sc + 256;    // 30
    float* wsh = sc + 288;    // 80
    const int tid = threadIdx.x;
    const float* h0 = &g_h0[((size_t)t*Bn + b)*Hn];

    int r = tid & 31, q = tid >> 5;           // q 0..7, chunks of 64
    float s = 0.f;
    if (r < 30) {
        const float* wr = &W_att[(size_t)r*Hn + q*64];
        const float* hh = &h0[q*64];
        #pragma unroll 8
        for (int k = 0; k < 64; k++) s += hh[k] * wr[k];
    }
    red[tid] = s;
    __syncthreads();
    if (tid < 30) {
        float tot = b_att[tid];
        #pragma unroll
        for (int q2 = 0; q2 < 8; q2++) tot += red[tid + 32*q2];
        abk[tid] = expf(tot);
    }
    __syncthreads();
    if (tid < 10) {
        float kn = abk[20 + tid] * 0.05f + g_kap[b*KAn + tid];
        g_kap[b*KAn + tid] = kn;
        abk[20 + tid] = kn;
    }
    if (tid >= 32 && tid < 112) wsh[tid - 32] = 0.f;
    __syncthreads();
    if (tid < 100) {
        float uu = (float)tid;
        float phi = 0.f;
        #pragma unroll
        for (int a = 0; a < 10; a++) {
            float d = abk[20 + a] - uu;
            phi += abk[a] * expf(-abk[10 + a] * d * d);
        }
        float m = cmask[(size_t)b*Un + tid];
        phi *= m * m;
        atomicAdd(&wsh[chars[(size_t)b*Un + tid]], phi);
    }
    __syncthreads();
    if (tid < 80) g_w[((size_t)t*Bn + b)*Vn + tid] = wsh[tid];
}

__global__ __launch_bounds__(256, 1)
void k_scan0(const float* __restrict__ strokes, const float* __restrict__ b0v,
             const float* __restrict__ W_att, const float* __restrict__ b_att,
             const int* __restrict__ chars, const float* __restrict__ cmask)
{
    extern __shared__ float sm[];
    float* ws  = sm;                          // [k][32]  (u*4+g packed)
    float* ws0 = sm + WS_F;
    float* xs  = sm + WS_F + WS0_F;           // [32][100]
    float* hs  = sm + WS_F + WS0_F + XS_F;    // [32][516]

    const int bt  = blockIdx.x >> 6;
    const int ht  = blockIdx.x & 63;
    const int tid = threadIdx.x;
    const int u   = tid & 7;
    const int bl  = tid >> 3;                 // 0..31
    const int b   = bt*32 + bl;

    for (int idx = tid; idx < WS_F; idx += 256)
        ws[idx] = g_Whp0[(size_t)(idx >> 5)*Gn + ht*32 + (idx & 31)];
    for (int idx = tid; idx < WS0_F; idx += 256)
        ws0[idx] = g_Wxp0[(size_t)(idx >> 5)*Gn + ht*32 + (idx & 31)];

    unsigned long long bias01, bias23;
    {
        float bi = b0v[       ht*8 + u];
        float bf = b0v[ Hn  + ht*8 + u];
        float bg2= b0v[2*Hn + ht*8 + u];
        float bo = b0v[3*Hn + ht*8 + u];
        bias01 = pack2(bi, bf);
        bias23 = pack2(bg2, bo);
    }
    if (ht < 32 && tid < KAn) g_kap[(bt*32 + ht)*KAn + tid] = 0.f;
    float c = 0.f;
    unsigned ep = 0;
    __syncthreads();

    const int row  = bl*516;
    const int xrow = bl*100;
    const ulonglong2* wv  = (const ulonglong2*)ws;   // idx k*8+u
    const ulonglong2* wv0 = (const ulonglong2*)ws0;

    for (int t = 0; t < Tn; t++) {
        // stage x = [strokes(3) | w_prev(80) | pad0]
        for (int idx = tid; idx < 32*96; idx += 256) {
            int bl2 = idx / 96, k = idx - bl2*96;
            int b2 = bt*32 + bl2;
            float v = 0.f;
            if (k < 3)                 v = strokes[((size_t)b2*Tn + t)*3 + k];
            else if (k < 83 && t > 0)  v = g_w[((size_t)(t-1)*Bn + b2)*Vn + (k-3)];
            xs[bl2*100 + k] = v;
        }
        if (t > 0) {
            const float* hp = &g_h0[((size_t)(t-1)*Bn + bt*32)*Hn];
            for (int idx = tid*4; idx < 32*512; idx += 1024) {
                int bl2 = idx >> 9, k = idx & 511;
                float4 v = *(const float4*)&hp[(size_t)bl2*Hn + k];
                *(float4*)&hs[bl2*516 + k] = v;
            }
        }
        __syncthreads();

        unsigned long long a01 = bias01, a23 = bias23;

        // x part (k = 96 padded)
        #pragma unroll 8
        for (int k = 0; k < 96; k++) {
            ulonglong2 w = wv0[k*8 + u];
            float x = xs[xrow + k];
            unsigned long long xx = pack2(x, x);
            fma2(a01, xx, w.x);
            fma2(a23, xx, w.y);
        }
        // recurrent part
        if (t > 0) {
            #pragma unroll 8
            for (int k = 0; k < 512; k++) {
                ulonglong2 w = wv[k*8 + u];
                float x = hs[row + k];
                unsigned long long xx = pack2(x, x);
                fma2(a01, xx, w.x);
                fma2(a23, xx, w.y);
            }
        }
        // state update
        {
            float2 g01 = unpk(a01), g23 = unpk(a23);
            float ig = sigf(g01.x), fg = sigf(g01.y);
            float gg = tanhf(g23.x), og = sigf(g23.y);
            c = fg*c + ig*gg;
            g_h0[((size_t)t*Bn + b)*Hn + ht*8 + u] = og * tanhf(c);
        }
        ep++;
        grid_bar(bt, ht, ep);                 // h0[t] done for this b-tile

        if (ht < 32)
            attn_step(t, bt*32 + ht, W_att, b_att, chars, cmask, hs);
        ep++;
        grid_bar(bt, ht, ep);                 // w[t] done for this b-tile
    }
}

// -------------------- persistent scan: layers 1/2 ---------------------------
__global__ __launch_bounds__(256, 1)
void k_scan12(int layer, unsigned epbase)
{
    extern __shared__ float sm[];
    float* ws = sm;              // [k][32]
    float* hs = sm + WS_F;       // [32][516]

    const float* whp  = (layer == 1) ? g_Whp1 : g_Whp2;
    float*       hseq = (layer == 1) ? g_h1   : g_h2;

    const int bt  = blockIdx.x >> 6;
    const int ht  = blockIdx.x & 63;
    const int tid = threadIdx.x;
    const int u   = tid & 7;
    const int bl  = tid >> 3;
    const int b   = bt*32 + bl;

    for (int idx = tid; idx < WS_F; idx += 256)
        ws[idx] = whp[(size_t)(idx >> 5)*Gn + ht*32 + (idx & 31)];
    float c = 0.f;
    unsigned ep = epbase;
    __syncthreads();

    const int row = bl*516;
    const ulonglong2* wv = (const ulonglong2*)ws;

    for (int t = 0; t < Tn; t++) {
        // gate init from precomputed projection: one LDG.128, issued early
        float4 pv = *(const float4*)&g_pre[(((size_t)t*Bn + b)*Hn + ht*8 + u)*4];

        if (t > 0) {
            const float* hp = &hseq[((size_t)(t-1)*Bn + bt*32)*Hn];
            for (int idx = tid*4; idx < 32*512; idx += 1024) {
                int bl2 = idx >> 9, k = idx & 511;
                float4 v = *(const float4*)&hp[(size_t)bl2*Hn + k];
                *(float4*)&hs[bl2*516 + k] = v;
            }
        }
        __syncthreads();

        unsigned long long a01 = pack2(pv.x, pv.y);
        unsigned long long a23 = pack2(pv.z, pv.w);

        if (t > 0) {
            #pragma unroll 8
            for (int k = 0; k < 512; k++) {
                ulonglong2 w = wv[k*8 + u];
                float x = hs[row + k];
                unsigned long long xx = pack2(x, x);
                fma2(a01, xx, w.x);
                fma2(a23, xx, w.y);
            }
        }
        {
            float2 g01 = unpk(a01), g23 = unpk(a23);
            float ig = sigf(g01.x), fg = sigf(g01.y);
            float gg = tanhf(g23.x), og = sigf(g23.y);
            c = fg*c + ig*gg;
            hseq[((size_t)t*Bn + b)*Hn + ht*8 + u] = og * tanhf(c);
        }
        ep++;
        grid_bar(bt, ht, ep);
    }
}

// -------------------- cat fill ------------------------------------------------
__global__ void k_fill_cat0(const float* __restrict__ strokes)
{
    size_t idx = (size_t)blockIdx.x * 256 + threadIdx.x;  // over T*B*608
    if (idx >= (size_t)Tn*Bn*K1P) return;
    int k = (int)(idx % K1P);
    size_t n = idx / K1P;
    int t = (int)(n >> 6), b = (int)(n & 63);
    float v = 0.f;
    if (k < 3)        v = strokes[((size_t)b*Tn + t)*3 + k];
    else if (k < 83)  v = g_w[n*Vn + (k-3)];
    else if (k < 595) v = g_h0[n*Hn + (k-83)];
    g_cat[idx] = v;
}

__global__ void k_fill_cat_h1()
{
    size_t idx = (size_t)blockIdx.x * 256 + threadIdx.x;  // over T*B*512
    if (idx >= (size_t)Tn*Bn*Hn) return;
    size_t n = idx >> 9;
    int k = (int)(idx & 511);
    g_cat[n*K1P + 83 + k] = g_h1[idx];
}

// -------------------- batched GEMM: pre = cat @ Wih^T + b -------------------
// output repacked to [n][unit(512)][gate(4)]
__global__ __launch_bounds__(256, 2)
void k_gemm_pre(const float* __restrict__ Wih, const float* __restrict__ bias)
{
    const int n0 = blockIdx.x * 64;
    const int j0 = blockIdx.y * 64;
    const int tid = threadIdx.x;
    const int tm = tid >> 4, tn = tid & 15;
    const int mload = tid >> 2;
    const int kq = (tid & 3) * 4;

    __shared__ float As[16][68];
    __shared__ float Bs[16][68];

    unsigned long long acc2[4][2];
    #pragma unroll
    for (int i = 0; i < 4; i++) { acc2[i][0] = 0ull; acc2[i][1] = 0ull; }

    for (int k0 = 0; k0 < K1P; k0 += 16) {
        float4 av = *(const float4*)&g_cat[(size_t)(n0+mload)*K1P + k0 + kq];
        As[kq+0][mload] = av.x; As[kq+1][mload] = av.y;
        As[kq+2][mload] = av.z; As[kq+3][mload] = av.w;

        const float* bptr = &Wih[(size_t)(j0+mload)*K1 + k0 + kq];
        #pragma unroll
        for (int i = 0; i < 4; i++) {
            int k = k0 + kq + i;
            Bs[kq+i][mload] = (k < K1) ? bptr[i] : 0.f;
        }
        __syncthreads();
        #pragma unroll
        for (int kk = 0; kk < 16; kk++) {
            float4 a4 = *(const float4*)&As[kk][tm*4];
            ulonglong2 b2 = *(const ulonglong2*)&Bs[kk][tn*4];
            unsigned long long ax;
            ax = pack2(a4.x, a4.x); fma2(acc2[0][0], ax, b2.x); fma2(acc2[0][1], ax, b2.y);
            ax = pack2(a4.y, a4.y); fma2(acc2[1][0], ax, b2.x); fma2(acc2[1][1], ax, b2.y);
            ax = pack2(a4.z, a4.z); fma2(acc2[2][0], ax, b2.x); fma2(acc2[2][1], ax, b2.y);
            ax = pack2(a4.w, a4.w); fma2(acc2[3][0], ax, b2.x); fma2(acc2[3][1], ax, b2.y);
        }
        __syncthreads();
    }

    const int g = j0 >> 9;   // gate index (constant per block)
    #pragma unroll
    for (int i = 0; i < 4; i++) {
        int n = n0 + tm*4 + i;
        float2 c01 = unpk(acc2[i][0]);
        float2 c23 = unpk(acc2[i][1]);
        float cv[4] = {c01.x, c01.y, c23.x, c23.y};
        #pragma unroll
        for (int jj = 0; jj < 4; jj++) {
            int j = j0 + tn*4 + jj;
            int unit = j & 511;
            g_pre[((size_t)n*Hn + unit)*4 + g] = cv[jj] + bias[j];
        }
    }
}

// -------------------- FC GEMM: fcraw = [h0|h1|h2] @ Wfc^T + b ---------------
__global__ __launch_bounds__(256, 2)
void k_gemm_fc(const float* __restrict__ Wfc, const float* __restrict__ bfc)
{
    const int n0 = blockIdx.x * 64;
    const int j0 = blockIdx.y * 64;
    const int tid = threadIdx.x;
    const int tm = tid >> 4, tn = tid & 15;
    const int mload = tid >> 2;
    const int kq = (tid & 3) * 4;

    __shared__ float As[16][68];
    __shared__ float Bs[16][68];

    unsigned long long acc2[4][2];
    #pragma unroll
    for (int i = 0; i < 4; i++) { acc2[i][0] = 0ull; acc2[i][1] = 0ull; }

    for (int k0 = 0; k0 < FCK; k0 += 16) {
        const float* hsrc = (k0 < 512) ? g_h0 : (k0 < 1024) ? g_h1 : g_h2;
        int krel = (k0 & 511) + kq;
        float4 av = *(const float4*)&hsrc[(size_t)(n0+mload)*Hn + krel];
        As[kq+0][mload] = av.x; As[kq+1][mload] = av.y;
        As[kq+2][mload] = av.z; As[kq+3][mload] = av.w;

        int rowj = j0 + mload;
        if (rowj < OUTC) {
            const float* bptr = &Wfc[(size_t)rowj*FCK + k0 + kq];
            Bs[kq+0][mload] = bptr[0]; Bs[kq+1][mload] = bptr[1];
            Bs[kq+2][mload] = bptr[2]; Bs[kq+3][mload] = bptr[3];
        } else {
            Bs[kq+0][mload] = 0.f; Bs[kq+1][mload] = 0.f;
            Bs[kq+2][mload] = 0.f; Bs[kq+3][mload] = 0.f;
        }
        __syncthreads();
        #pragma unroll
        for (int kk = 0; kk < 16; kk++) {
            float4 a4 = *(const float4*)&As[kk][tm*4];
            ulonglong2 b2 = *(const ulonglong2*)&Bs[kk][tn*4];
            unsigned long long ax;
            ax = pack2(a4.x, a4.x); fma2(acc2[0][0], ax, b2.x); fma2(acc2[0][1], ax, b2.y);
            ax = pack2(a4.y, a4.y); fma2(acc2[1][0], ax, b2.x); fma2(acc2[1][1], ax, b2.y);
            ax = pack2(a4.z, a4.z); fma2(acc2[2][0], ax, b2.x); fma2(acc2[2][1], ax, b2.y);
            ax = pack2(a4.w, a4.w); fma2(acc2[3][0], ax, b2.x); fma2(acc2[3][1], ax, b2.y);
        }
        __syncthreads();
    }

    #pragma unroll
    for (int i = 0; i < 4; i++) {
        int n = n0 + tm*4 + i;
        float2 c01 = unpk(acc2[i][0]);
        float2 c23 = unpk(acc2[i][1]);
        float cv[4] = {c01.x, c01.y, c23.x, c23.y};
        #pragma unroll
        for (int jj = 0; jj < 4; jj++) {
            int jcol = j0 + tn*4 + jj;
            if (jcol < OUTC)
                g_fcraw[(size_t)n*OUTC + jcol] = cv[jj] + bfc[jcol];
        }
    }
}

// -------------------- epilogue ------------------------------------------------
__global__ void k_epilogue(float* __restrict__ out)
{
    int n = blockIdx.x * 128 + threadIdx.x;
    if (n >= Tn*Bn) return;
    const float* r = &g_fcraw[(size_t)n*OUTC];
    int t = n >> 6, b = n & 63;
    float* o = &out[((size_t)b*Tn + t)*OUTC];

    float mx = -1e30f;
    #pragma unroll
    for (int k = 0; k < 20; k++) mx = fmaxf(mx, r[80 + k]);
    float se = 0.f;
    #pragma unroll
    for (int k = 0; k < 20; k++) se += expf(r[80 + k] - mx);
    float lse = mx + logf(se);
    #pragma unroll
    for (int k = 0; k < 20; k++) o[k] = r[80 + k] - lse;          // log_pi
    #pragma unroll
    for (int k = 0; k < 40; k++) o[20 + k] = r[k];                // mu
    #pragma unroll
    for (int k = 0; k < 40; k++) o[60 + k] = r[40 + k];           // log_sigma
    #pragma unroll
    for (int k = 0; k < 20; k++) o[100 + k] = tanhf(r[100 + k]);  // rho
    o[120] = 1.f / (1.f + expf(r[120]));                          // sigmoid(-eos)
}

// -------------------- host launch ---------------------------------------------
extern "C" void kernel_launch(void* const* d_in, const int* in_sizes, int n_in,
                              void* d_out, int out_size)
{
    const int*   chars   = (const int*)  d_in[0];
    const float* cmask   = (const float*)d_in[1];
    const float* strokes = (const float*)d_in[2];
    // d_in[3] strokes_mask unused by reference
    const float* W_ih0   = (const float*)d_in[4];
    const float* W_hh0   = (const float*)d_in[5];
    const float* b0      = (const float*)d_in[6];
    const float* W_att   = (const float*)d_in[7];
    const float* b_att   = (const float*)d_in[8];
    const float* W_ih1   = (const float*)d_in[9];
    const float* W_hh1   = (const float*)d_in[10];
    const float* b1      = (const float*)d_in[11];
    const float* W_ih2   = (const float*)d_in[12];
    const float* W_hh2   = (const float*)d_in[13];
    const float* b2      = (const float*)d_in[14];
    const float* W_fc    = (const float*)d_in[15];
    const float* b_fc    = (const float*)d_in[16];
    float* out = (float*)d_out;

    const int SM0  = (WS_F + WS0_F + XS_F + HS_F) * 4;   // 156,672 B
    const int SM12 = (WS_F + HS_F) * 4;                  // 131,584 B
    cudaFuncSetAttribute(k_scan0,  cudaFuncAttributeMaxDynamicSharedMemorySize, SM0);
    cudaFuncSetAttribute(k_scan12, cudaFuncAttributeMaxDynamicSharedMemorySize, SM12);

    // preps needed before scan0 (launch order puts k_scan0 at index 3 so the
    // ncu capture slot lands on the dominant kernel)
    k_prep_whh<<<(Hn*Gn + 255)/256, 256>>>(W_hh0, 0);
    k_prep_wx0<<<(96*Gn + 255)/256, 256>>>(W_ih0);       // also zeroes flags
    k_prep_whh<<<(Hn*Gn + 255)/256, 256>>>(W_hh1, 1);

    // layer 0 scan (lstm0 + attention), persistent — launch index 3
    k_scan0<<<128, 256, SM0>>>(strokes, b0, W_att, b_att, chars, cmask);

    k_prep_whh<<<(Hn*Gn + 255)/256, 256>>>(W_hh2, 2);

    // layer 1
    {
        size_t tot = (size_t)Tn*Bn*K1P;
        k_fill_cat0<<<(unsigned)((tot + 255)/256), 256>>>(strokes);
    }
    k_gemm_pre<<<dim3(Tn*Bn/64, Gn/64), 256>>>(W_ih1, b1);
    k_scan12<<<128, 256, SM12>>>(1, 1600u);

    // layer 2
    {
        size_t tot = (size_t)Tn*Bn*Hn;
        k_fill_cat_h1<<<(unsigned)((tot + 255)/256), 256>>>();
    }
    k_gemm_pre<<<dim3(Tn*Bn/64, Gn/64), 256>>>(W_ih2, b2);
    k_scan12<<<128, 256, SM12>>>(2, 2400u);

    // head
    k_gemm_fc<<<dim3(Tn*Bn/64, 2), 256>>>(W_fc, b_fc);
    k_epilogue<<<(Tn*Bn + 127)/128, 128>>>(out);
}

// round 7
// speedup vs baseline: 1.2759x; 1.2759x over previous
#include <cuda_runtime.h>
#include <cuda_bf16.h>
#include <math.h>

// ---------------------------------------------------------------------------
// Handwriting synthesis network (Graves attention, 3x LSTM-512, GMM head)
// B=64 T=800 U=100 V=80 H=512 KA=10 KO=20
// Persistent scans: warp-per-(u-pair,k-half), lanes=batches, broadcast weights,
// producer-transposed h (g_hT) for cheap staging, f32x2 math, flag barrier.
// ---------------------------------------------------------------------------

#define Bn   64
#define Tn   800
#define Un   100
#define Vn   80
#define Hn   512
#define KAn  10
#define Gn   2048          // 4*H
#define K1   595           // 3+V+H
#define K1P  608           // padded
#define FCK  1536          // 3*H
#define OUTC 121

// -------------------- f32x2 helpers -----------------------------------------
__device__ __forceinline__ unsigned long long pack2(float x, float y)
{
    unsigned long long r;
    asm("mov.b64 %0, {%1, %2};" : "=l"(r) : "f"(x), "f"(y));
    return r;
}
__device__ __forceinline__ void fma2(unsigned long long& d,
                                     unsigned long long a, unsigned long long b)
{
    asm("fma.rn.f32x2 %0, %1, %2, %0;" : "+l"(d) : "l"(a), "l"(b));
}
__device__ __forceinline__ float2 unpk(unsigned long long v)
{
    float2 f;
    asm("mov.b64 {%0, %1}, %2;" : "=f"(f.x), "=f"(f.y) : "l"(v));
    return f;
}
__device__ __forceinline__ unsigned long long add2(unsigned long long a,
                                                   unsigned long long b)
{
    unsigned long long r;
    asm("add.rn.f32x2 %0, %1, %2;" : "=l"(r) : "l"(a), "l"(b));
    return r;
}

// -------------------- static device scratch --------------------------------
__device__ float g_h0[(size_t)Tn*Bn*Hn];
__device__ float g_h1[(size_t)Tn*Bn*Hn];
__device__ float g_h2[(size_t)Tn*Bn*Hn];
__device__ float g_w [(size_t)Tn*Bn*Vn];
__device__ float g_hT[2*Hn*Bn];            // transposed h, double buffered
__device__ float g_wT[2*Vn*Bn];            // transposed w, double buffered
__device__ float g_kap[Bn*KAn];
// packed weight layouts: [k][ht(64)][u(8)][g(4)]
__device__ float g_Whp0[(size_t)Hn*Gn];
__device__ float g_Whp1[(size_t)Hn*Gn];
__device__ float g_Whp2[(size_t)Hn*Gn];
__device__ float g_Wxp0[(size_t)96*Gn];
__device__ float g_cat[(size_t)Tn*Bn*K1P];
__device__ float g_pre[(size_t)Tn*Bn*Gn];      // layout [n][unit(512)][gate(4)]
__device__ float g_fcraw[(size_t)Tn*Bn*OUTC];

// flag-array barrier: 2 groups x 64 blocks, one 128B line per flag
__device__ unsigned g_flag[2*64*32];

__device__ __forceinline__ float sigf(float x) { return 1.f/(1.f+expf(-x)); }

__device__ __forceinline__ void grid_bar(int grp, int myht, unsigned ep)
{
    __syncthreads();
    const int tid = threadIdx.x;
    if (tid == 0) {
        unsigned* f = &g_flag[(grp*64 + myht)*32];
        asm volatile("st.release.gpu.u32 [%0], %1;" :: "l"(f), "r"(ep) : "memory");
    }
    if (tid < 64) {
        unsigned* f = &g_flag[(grp*64 + tid)*32];
        unsigned v;
        do {
            asm volatile("ld.acquire.gpu.u32 %0, [%1];" : "=r"(v) : "l"(f) : "memory");
        } while (v < ep);
    }
    __syncthreads();
}

// -------------------- prep kernels ------------------------------------------
__global__ void k_prep_whh(const float* __restrict__ W, int layer)
{
    int idx = blockIdx.x * 256 + threadIdx.x;
    if (idx >= Hn*Gn) return;
    int g  = idx & 3;
    int u  = (idx >> 2) & 7;
    int ht = (idx >> 5) & 63;
    int k  = idx >> 11;
    float v = W[(size_t)(g*Hn + ht*8 + u)*Hn + k];
    if (layer == 0)      g_Whp0[idx] = v;
    else if (layer == 1) g_Whp1[idx] = v;
    else                 g_Whp2[idx] = v;
}

__global__ void k_prep_wx0(const float* __restrict__ Wih0)
{
    int idx = blockIdx.x * 256 + threadIdx.x;
    if (idx < 2*64*32) g_flag[idx] = 0;        // reset barrier flags each run
    if (idx >= 96*Gn) return;
    int g  = idx & 3;
    int u  = (idx >> 2) & 7;
    int ht = (idx >> 5) & 63;
    int k  = idx >> 11;
    g_Wxp0[idx] = (k < 83) ? Wih0[(size_t)(g*Hn + ht*8 + u)*83 + k] : 0.f;
}

// -------------------- persistent scan shapes ---------------------------------
// grid 128 = (bt 0..1)*64 + (ht 0..63). block 256 threads.
// thread: bl = tid&31 (batch), q = (tid>>5)&3 (u-pair), s = tid>>7 (k-half).
#define WS_F   (512*32)
#define WS0_F  (96*32)
#define HS_F   (512*32)
#define XS_F   (96*32)
#define RED_F  (128*8)
#define ATT_F  384

__device__ __forceinline__ void attn_step(
    int t, int b, const float* __restrict__ W_att, const float* __restrict__ b_att,
    const int* __restrict__ chars, const float* __restrict__ cmask, float* sc)
{
    float* red = sc;          // 256
    float* abk = sc + 256;    // 30
    float* wsh = sc + 288;    // 80
    const int tid = threadIdx.x;
    const float* h0 = &g_h0[((size_t)t*Bn + b)*Hn];

    int r = tid & 31, q = tid >> 5;           // q 0..7, chunks of 64
    float s = 0.f;
    if (r < 30) {
        const float* wr = &W_att[(size_t)r*Hn + q*64];
        const float* hh = &h0[q*64];
        #pragma unroll 8
        for (int k = 0; k < 64; k++) s += hh[k] * wr[k];
    }
    red[tid] = s;
    __syncthreads();
    if (tid < 30) {
        float tot = b_att[tid];
        #pragma unroll
        for (int q2 = 0; q2 < 8; q2++) tot += red[tid + 32*q2];
        abk[tid] = expf(tot);
    }
    __syncthreads();
    if (tid < 10) {
        float kn = abk[20 + tid] * 0.05f + g_kap[b*KAn + tid];
        g_kap[b*KAn + tid] = kn;
        abk[20 + tid] = kn;
    }
    if (tid >= 32 && tid < 112) wsh[tid - 32] = 0.f;
    __syncthreads();
    if (tid < 100) {
        float uu = (float)tid;
        float phi = 0.f;
        #pragma unroll
        for (int a = 0; a < 10; a++) {
            float d = abk[20 + a] - uu;
            phi += abk[a] * expf(-abk[10 + a] * d * d);
        }
        float m = cmask[(size_t)b*Un + tid];
        phi *= m * m;
        atomicAdd(&wsh[chars[(size_t)b*Un + tid]], phi);
    }
    __syncthreads();
    if (tid < 80) {
        float v = wsh[tid];
        g_w[((size_t)t*Bn + b)*Vn + tid] = v;
        g_wT[(t&1)*Vn*Bn + tid*Bn + b] = v;       // transposed copy
    }
}

__global__ __launch_bounds__(256, 1)
void k_scan0(const float* __restrict__ strokes, const float* __restrict__ b0v,
             const float* __restrict__ W_att, const float* __restrict__ b_att,
             const int* __restrict__ chars, const float* __restrict__ cmask)
{
    extern __shared__ float sm[];
    float* ws   = sm;                               // [k][32]
    float* ws0  = sm + WS_F;                        // [k][32]
    float* hs   = sm + WS_F + WS0_F;                // [k][32]
    float* xs   = sm + WS_F + WS0_F + HS_F;         // [k][32]
    float* red  = sm + WS_F + WS0_F + HS_F + XS_F;  // [128][8]
    float* atts = red + RED_F;                      // 384

    const int bt  = blockIdx.x >> 6;
    const int ht  = blockIdx.x & 63;
    const int tid = threadIdx.x;
    const int bl  = tid & 31;
    const int q   = (tid >> 5) & 3;
    const int s   = tid >> 7;
    const int b   = bt*32 + bl;

    for (int idx = tid; idx < WS_F; idx += 256)
        ws[idx] = g_Whp0[(size_t)(idx >> 5)*Gn + ht*32 + (idx & 31)];
    for (int idx = tid; idx < WS0_F; idx += 256)
        ws0[idx] = g_Wxp0[(size_t)(idx >> 5)*Gn + ht*32 + (idx & 31)];

    // bias for this thread's two units (s==0 threads seed acc with it)
    const int u0 = ht*8 + q*2, u1 = u0 + 1;
    unsigned long long b0_01 = 0, b0_23 = 0, b1_01 = 0, b1_23 = 0;
    if (s == 0) {
        b0_01 = pack2(b0v[u0], b0v[Hn + u0]);
        b0_23 = pack2(b0v[2*Hn + u0], b0v[3*Hn + u0]);
        b1_01 = pack2(b0v[u1], b0v[Hn + u1]);
        b1_23 = pack2(b0v[2*Hn + u1], b0v[3*Hn + u1]);
    }
    if (ht < 32 && tid < KAn) g_kap[(bt*32 + ht)*KAn + tid] = 0.f;
    float c0 = 0.f, c1 = 0.f;
    unsigned ep = 0;
    __syncthreads();

    for (int t = 0; t < Tn; t++) {
        // ---- stage x tile [96][32]: strokes(3) | w_prev(80) | pad
        for (int idx = tid; idx < XS_F; idx += 256) {
            int k = idx >> 5, cc = idx & 31;
            int b2 = bt*32 + cc;
            float v = 0.f;
            if (k < 3)                 v = strokes[((size_t)b2*Tn + t)*3 + k];
            else if (k < 83 && t > 0)  v = __ldcg(&g_wT[((t-1)&1)*Vn*Bn + (k-3)*Bn + b2]);
            xs[idx] = v;
        }
        // ---- stage h tile [512][32] from transposed gmem
        if (t > 0) {
            const float* src = &g_hT[((t-1)&1)*Hn*Bn + bt*32];
            #pragma unroll
            for (int j = 0; j < 16; j++) {
                int idx = tid*4 + j*1024;
                int k = idx >> 5, cc = idx & 31;
                float4 v = __ldcg((const float4*)&src[k*64 + cc]);
                *(float4*)&hs[idx] = v;
            }
        }
        __syncthreads();

        unsigned long long a0_01 = b0_01, a0_23 = b0_23;
        unsigned long long a1_01 = b1_01, a1_23 = b1_23;

        // ---- x part: k in [s*48, s*48+48)
        {
            const int k0 = s*48;
            #pragma unroll 8
            for (int k = k0; k < k0 + 48; k++) {
                ulonglong2 w0 = *(const ulonglong2*)&ws0[k*32 + q*8];
                ulonglong2 w1 = *(const ulonglong2*)&ws0[k*32 + q*8 + 4];
                float x = xs[k*32 + bl];
                unsigned long long xx = pack2(x, x);
                fma2(a0_01, xx, w0.x); fma2(a0_23, xx, w0.y);
                fma2(a1_01, xx, w1.x); fma2(a1_23, xx, w1.y);
            }
        }
        // ---- recurrent part: k in [s*256, s*256+256)
        if (t > 0) {
            const int k0 = s*256;
            #pragma unroll 8
            for (int k = k0; k < k0 + 256; k++) {
                ulonglong2 w0 = *(const ulonglong2*)&ws[k*32 + q*8];
                ulonglong2 w1 = *(const ulonglong2*)&ws[k*32 + q*8 + 4];
                float x = hs[k*32 + bl];
                unsigned long long xx = pack2(x, x);
                fma2(a0_01, xx, w0.x); fma2(a0_23, xx, w0.y);
                fma2(a1_01, xx, w1.x); fma2(a1_23, xx, w1.y);
            }
        }
        // ---- reduce the two k-halves
        if (s == 1) {
            float* rp = &red[(tid - 128)*8];
            *(unsigned long long*)(rp+0) = a0_01;
            *(unsigned long long*)(rp+2) = a0_23;
            *(unsigned long long*)(rp+4) = a1_01;
            *(unsigned long long*)(rp+6) = a1_23;
        }
        __syncthreads();
        if (s == 0) {
            const float* rp = &red[tid*8];
            a0_01 = add2(a0_01, *(const unsigned long long*)(rp+0));
            a0_23 = add2(a0_23, *(const unsigned long long*)(rp+2));
            a1_01 = add2(a1_01, *(const unsigned long long*)(rp+4));
            a1_23 = add2(a1_23, *(const unsigned long long*)(rp+6));

            float2 g01 = unpk(a0_01), g23 = unpk(a0_23);
            float ig = sigf(g01.x), fg = sigf(g01.y);
            float gg = tanhf(g23.x), og = sigf(g23.y);
            c0 = fg*c0 + ig*gg;
            float h0v = og * tanhf(c0);
            g01 = unpk(a1_01); g23 = unpk(a1_23);
            ig = sigf(g01.x); fg = sigf(g01.y);
            gg = tanhf(g23.x); og = sigf(g23.y);
            c1 = fg*c1 + ig*gg;
            float h1v = og * tanhf(c1);

            g_h0[((size_t)t*Bn + b)*Hn + u0] = h0v;
            g_h0[((size_t)t*Bn + b)*Hn + u1] = h1v;
            float* dst = &g_hT[(t&1)*Hn*Bn];
            dst[u0*64 + b] = h0v;
            dst[u1*64 + b] = h1v;
        }
        ep++;
        grid_bar(bt, ht, ep);                 // h0[t] done for this b-tile

        if (ht < 32)
            attn_step(t, bt*32 + ht, W_att, b_att, chars, cmask, atts);
        ep++;
        grid_bar(bt, ht, ep);                 // w[t] done for this b-tile
    }
}

// -------------------- persistent scan: layers 1/2 ---------------------------
__global__ __launch_bounds__(256, 1)
void k_scan12(int layer, unsigned epbase)
{
    extern __shared__ float sm[];
    float* ws  = sm;                 // [k][32]
    float* hs  = sm + WS_F;          // [k][32]
    float* red = sm + WS_F + HS_F;   // [128][8]

    const float* whp  = (layer == 1) ? g_Whp1 : g_Whp2;
    float*       hseq = (layer == 1) ? g_h1   : g_h2;

    const int bt  = blockIdx.x >> 6;
    const int ht  = blockIdx.x & 63;
    const int tid = threadIdx.x;
    const int bl  = tid & 31;
    const int q   = (tid >> 5) & 3;
    const int s   = tid >> 7;
    const int b   = bt*32 + bl;
    const int u0  = ht*8 + q*2, u1 = u0 + 1;

    for (int idx = tid; idx < WS_F; idx += 256)
        ws[idx] = whp[(size_t)(idx >> 5)*Gn + ht*32 + (idx & 31)];
    float c0 = 0.f, c1 = 0.f;
    unsigned ep = epbase;
    __syncthreads();

    for (int t = 0; t < Tn; t++) {
        unsigned long long a0_01 = 0, a0_23 = 0, a1_01 = 0, a1_23 = 0;
        if (s == 0) {
            const float* pp = &g_pre[(((size_t)t*Bn + b)*Hn)*4];
            float4 p0 = *(const float4*)&pp[u0*4];
            float4 p1 = *(const float4*)&pp[u1*4];
            a0_01 = pack2(p0.x, p0.y); a0_23 = pack2(p0.z, p0.w);
            a1_01 = pack2(p1.x, p1.y); a1_23 = pack2(p1.z, p1.w);
        }

        if (t > 0) {
            const float* src = &g_hT[((t-1)&1)*Hn*Bn + bt*32];
            #pragma unroll
            for (int j = 0; j < 16; j++) {
                int idx = tid*4 + j*1024;
                int k = idx >> 5, cc = idx & 31;
                float4 v = __ldcg((const float4*)&src[k*64 + cc]);
                *(float4*)&hs[idx] = v;
            }
        }
        __syncthreads();

        if (t > 0) {
            const int k0 = s*256;
            #pragma unroll 8
            for (int k = k0; k < k0 + 256; k++) {
                ulonglong2 w0 = *(const ulonglong2*)&ws[k*32 + q*8];
                ulonglong2 w1 = *(const ulonglong2*)&ws[k*32 + q*8 + 4];
                float x = hs[k*32 + bl];
                unsigned long long xx = pack2(x, x);
                fma2(a0_01, xx, w0.x); fma2(a0_23, xx, w0.y);
                fma2(a1_01, xx, w1.x); fma2(a1_23, xx, w1.y);
            }
        }
        if (s == 1) {
            float* rp = &red[(tid - 128)*8];
            *(unsigned long long*)(rp+0) = a0_01;
            *(unsigned long long*)(rp+2) = a0_23;
            *(unsigned long long*)(rp+4) = a1_01;
            *(unsigned long long*)(rp+6) = a1_23;
        }
        __syncthreads();
        if (s == 0) {
            const float* rp = &red[tid*8];
            a0_01 = add2(a0_01, *(const unsigned long long*)(rp+0));
            a0_23 = add2(a0_23, *(const unsigned long long*)(rp+2));
            a1_01 = add2(a1_01, *(const unsigned long long*)(rp+4));
            a1_23 = add2(a1_23, *(const unsigned long long*)(rp+6));

            float2 g01 = unpk(a0_01), g23 = unpk(a0_23);
            float ig = sigf(g01.x), fg = sigf(g01.y);
            float gg = tanhf(g23.x), og = sigf(g23.y);
            c0 = fg*c0 + ig*gg;
            float h0v = og * tanhf(c0);
            g01 = unpk(a1_01); g23 = unpk(a1_23);
            ig = sigf(g01.x); fg = sigf(g01.y);
            gg = tanhf(g23.x); og = sigf(g23.y);
            c1 = fg*c1 + ig*gg;
            float h1v = og * tanhf(c1);

            hseq[((size_t)t*Bn + b)*Hn + u0] = h0v;
            hseq[((size_t)t*Bn + b)*Hn + u1] = h1v;
            float* dst = &g_hT[(t&1)*Hn*Bn];
            dst[u0*64 + b] = h0v;
            dst[u1*64 + b] = h1v;
        }
        ep++;
        grid_bar(bt, ht, ep);
    }
}

// -------------------- cat fill ------------------------------------------------
__global__ void k_fill_cat0(const float* __restrict__ strokes)
{
    size_t idx = (size_t)blockIdx.x * 256 + threadIdx.x;  // over T*B*608
    if (idx >= (size_t)Tn*Bn*K1P) return;
    int k = (int)(idx % K1P);
    size_t n = idx / K1P;
    int t = (int)(n >> 6), b = (int)(n & 63);
    float v = 0.f;
    if (k < 3)        v = strokes[((size_t)b*Tn + t)*3 + k];
    else if (k < 83)  v = g_w[n*Vn + (k-3)];
    else if (k < 595) v = g_h0[n*Hn + (k-83)];
    g_cat[idx] = v;
}

__global__ void k_fill_cat_h1()
{
    size_t idx = (size_t)blockIdx.x * 256 + threadIdx.x;  // over T*B*512
    if (idx >= (size_t)Tn*Bn*Hn) return;
    size_t n = idx >> 9;
    int k = (int)(idx & 511);
    g_cat[n*K1P + 83 + k] = g_h1[idx];
}

// -------------------- batched GEMM: pre = cat @ Wih^T + b -------------------
// output packed [n][unit(512)][gate(4)]
__global__ __launch_bounds__(256, 2)
void k_gemm_pre(const float* __restrict__ Wih, const float* __restrict__ bias)
{
    const int n0 = blockIdx.x * 64;
    const int j0 = blockIdx.y * 64;
    const int tid = threadIdx.x;
    const int tm = tid >> 4, tn = tid & 15;
    const int mload = tid >> 2;
    const int kq = (tid & 3) * 4;

    __shared__ float As[16][68];
    __shared__ float Bs[16][68];

    unsigned long long acc2[4][2];
    #pragma unroll
    for (int i = 0; i < 4; i++) { acc2[i][0] = 0ull; acc2[i][1] = 0ull; }

    for (int k0 = 0; k0 < K1P; k0 += 16) {
        float4 av = *(const float4*)&g_cat[(size_t)(n0+mload)*K1P + k0 + kq];
        As[kq+0][mload] = av.x; As[kq+1][mload] = av.y;
        As[kq+2][mload] = av.z; As[kq+3][mload] = av.w;

        const float* bptr = &Wih[(size_t)(j0+mload)*K1 + k0 + kq];
        #pragma unroll
        for (int i = 0; i < 4; i++) {
            int k = k0 + kq + i;
            Bs[kq+i][mload] = (k < K1) ? bptr[i] : 0.f;
        }
        __syncthreads();
        #pragma unroll
        for (int kk = 0; kk < 16; kk++) {
            float4 a4 = *(const float4*)&As[kk][tm*4];
            ulonglong2 b2 = *(const ulonglong2*)&Bs[kk][tn*4];
            unsigned long long ax;
            ax = pack2(a4.x, a4.x); fma2(acc2[0][0], ax, b2.x); fma2(acc2[0][1], ax, b2.y);
            ax = pack2(a4.y, a4.y); fma2(acc2[1][0], ax, b2.x); fma2(acc2[1][1], ax, b2.y);
            ax = pack2(a4.z, a4.z); fma2(acc2[2][0], ax, b2.x); fma2(acc2[2][1], ax, b2.y);
            ax = pack2(a4.w, a4.w); fma2(acc2[3][0], ax, b2.x); fma2(acc2[3][1], ax, b2.y);
        }
        __syncthreads();
    }

    const int g = j0 >> 9;   // gate index
    #pragma unroll
    for (int i = 0; i < 4; i++) {
        int n = n0 + tm*4 + i;
        float2 c01 = unpk(acc2[i][0]);
        float2 c23 = unpk(acc2[i][1]);
        float cv[4] = {c01.x, c01.y, c23.x, c23.y};
        #pragma unroll
        for (int jj = 0; jj < 4; jj++) {
            int j = j0 + tn*4 + jj;
            int unit = j & 511;
            g_pre[((size_t)n*Hn + unit)*4 + g] = cv[jj] + bias[j];
        }
    }
}

// -------------------- FC GEMM: fcraw = [h0|h1|h2] @ Wfc^T + b ---------------
__global__ __launch_bounds__(256, 2)
void k_gemm_fc(const float* __restrict__ Wfc, const float* __restrict__ bfc)
{
    const int n0 = blockIdx.x * 64;
    const int j0 = blockIdx.y * 64;
    const int tid = threadIdx.x;
    const int tm = tid >> 4, tn = tid & 15;
    const int mload = tid >> 2;
    const int kq = (tid & 3) * 4;

    __shared__ float As[16][68];
    __shared__ float Bs[16][68];

    unsigned long long acc2[4][2];
    #pragma unroll
    for (int i = 0; i < 4; i++) { acc2[i][0] = 0ull; acc2[i][1] = 0ull; }

    for (int k0 = 0; k0 < FCK; k0 += 16) {
        const float* hsrc = (k0 < 512) ? g_h0 : (k0 < 1024) ? g_h1 : g_h2;
        int krel = (k0 & 511) + kq;
        float4 av = *(const float4*)&hsrc[(size_t)(n0+mload)*Hn + krel];
        As[kq+0][mload] = av.x; As[kq+1][mload] = av.y;
        As[kq+2][mload] = av.z; As[kq+3][mload] = av.w;

        int rowj = j0 + mload;
        if (rowj < OUTC) {
            const float* bptr = &Wfc[(size_t)rowj*FCK + k0 + kq];
            Bs[kq+0][mload] = bptr[0]; Bs[kq+1][mload] = bptr[1];
            Bs[kq+2][mload] = bptr[2]; Bs[kq+3][mload] = bptr[3];
        } else {
            Bs[kq+0][mload] = 0.f; Bs[kq+1][mload] = 0.f;
            Bs[kq+2][mload] = 0.f; Bs[kq+3][mload] = 0.f;
        }
        __syncthreads();
        #pragma unroll
        for (int kk = 0; kk < 16; kk++) {
            float4 a4 = *(const float4*)&As[kk][tm*4];
            ulonglong2 b2 = *(const ulonglong2*)&Bs[kk][tn*4];
            unsigned long long ax;
            ax = pack2(a4.x, a4.x); fma2(acc2[0][0], ax, b2.x); fma2(acc2[0][1], ax, b2.y);
            ax = pack2(a4.y, a4.y); fma2(acc2[1][0], ax, b2.x); fma2(acc2[1][1], ax, b2.y);
            ax = pack2(a4.z, a4.z); fma2(acc2[2][0], ax, b2.x); fma2(acc2[2][1], ax, b2.y);
            ax = pack2(a4.w, a4.w); fma2(acc2[3][0], ax, b2.x); fma2(acc2[3][1], ax, b2.y);
        }
        __syncthreads();
    }

    #pragma unroll
    for (int i = 0; i < 4; i++) {
        int n = n0 + tm*4 + i;
        float2 c01 = unpk(acc2[i][0]);
        float2 c23 = unpk(acc2[i][1]);
        float cv[4] = {c01.x, c01.y, c23.x, c23.y};
        #pragma unroll
        for (int jj = 0; jj < 4; jj++) {
            int jcol = j0 + tn*4 + jj;
            if (jcol < OUTC)
                g_fcraw[(size_t)n*OUTC + jcol] = cv[jj] + bfc[jcol];
        }
    }
}

// -------------------- epilogue ------------------------------------------------
__global__ void k_epilogue(float* __restrict__ out)
{
    int n = blockIdx.x * 128 + threadIdx.x;
    if (n >= Tn*Bn) return;
    const float* r = &g_fcraw[(size_t)n*OUTC];
    int t = n >> 6, b = n & 63;
    float* o = &out[((size_t)b*Tn + t)*OUTC];

    float mx = -1e30f;
    #pragma unroll
    for (int k = 0; k < 20; k++) mx = fmaxf(mx, r[80 + k]);
    float se = 0.f;
    #pragma unroll
    for (int k = 0; k < 20; k++) se += expf(r[80 + k] - mx);
    float lse = mx + logf(se);
    #pragma unroll
    for (int k = 0; k < 20; k++) o[k] = r[80 + k] - lse;          // log_pi
    #pragma unroll
    for (int k = 0; k < 40; k++) o[20 + k] = r[k];                // mu
    #pragma unroll
    for (int k = 0; k < 40; k++) o[60 + k] = r[40 + k];           // log_sigma
    #pragma unroll
    for (int k = 0; k < 20; k++) o[100 + k] = tanhf(r[100 + k]);  // rho
    o[120] = 1.f / (1.f + expf(r[120]));                          // sigmoid(-eos)
}

// -------------------- host launch ---------------------------------------------
extern "C" void kernel_launch(void* const* d_in, const int* in_sizes, int n_in,
                              void* d_out, int out_size)
{
    const int*   chars   = (const int*)  d_in[0];
    const float* cmask   = (const float*)d_in[1];
    const float* strokes = (const float*)d_in[2];
    // d_in[3] strokes_mask unused by reference
    const float* W_ih0   = (const float*)d_in[4];
    const float* W_hh0   = (const float*)d_in[5];
    const float* b0      = (const float*)d_in[6];
    const float* W_att   = (const float*)d_in[7];
    const float* b_att   = (const float*)d_in[8];
    const float* W_ih1   = (const float*)d_in[9];
    const float* W_hh1   = (const float*)d_in[10];
    const float* b1      = (const float*)d_in[11];
    const float* W_ih2   = (const float*)d_in[12];
    const float* W_hh2   = (const float*)d_in[13];
    const float* b2      = (const float*)d_in[14];
    const float* W_fc    = (const float*)d_in[15];
    const float* b_fc    = (const float*)d_in[16];
    float* out = (float*)d_out;

    const int SM0  = (WS_F + WS0_F + HS_F + XS_F + RED_F + ATT_F) * 4;  // 161,280 B
    const int SM12 = (WS_F + HS_F + RED_F) * 4;                          // 135,168 B
    cudaFuncSetAttribute(k_scan0,  cudaFuncAttributeMaxDynamicSharedMemorySize, SM0);
    cudaFuncSetAttribute(k_scan12, cudaFuncAttributeMaxDynamicSharedMemorySize, SM12);

    // preps (k_scan0 stays at launch index 3 for the ncu capture slot)
    k_prep_whh<<<(Hn*Gn + 255)/256, 256>>>(W_hh0, 0);
    k_prep_wx0<<<(96*Gn + 255)/256, 256>>>(W_ih0);       // also zeroes flags
    k_prep_whh<<<(Hn*Gn + 255)/256, 256>>>(W_hh1, 1);

    // layer 0 scan (lstm0 + attention), persistent
    k_scan0<<<128, 256, SM0>>>(strokes, b0, W_att, b_att, chars, cmask);

    k_prep_whh<<<(Hn*Gn + 255)/256, 256>>>(W_hh2, 2);

    // layer 1
    {
        size_t tot = (size_t)Tn*Bn*K1P;
        k_fill_cat0<<<(unsigned)((tot + 255)/256), 256>>>(strokes);
    }
    k_gemm_pre<<<dim3(Tn*Bn/64, Gn/64), 256>>>(W_ih1, b1);
    k_scan12<<<128, 256, SM12>>>(1, 1600u);

    // layer 2
    {
        size_t tot = (size_t)Tn*Bn*Hn;
        k_fill_cat_h1<<<(unsigned)((tot + 255)/256), 256>>>();
    }
    k_gemm_pre<<<dim3(Tn*Bn/64, Gn/64), 256>>>(W_ih2, b2);
    k_scan12<<<128, 256, SM12>>>(2, 2400u);

    // head
    k_gemm_fc<<<dim3(Tn*Bn/64, 2), 256>>>(W_fc, b_fc);
    k_epilogue<<<(Tn*Bn + 127)/128, 128>>>(out);
}

// round 8
// speedup vs baseline: 1.5356x; 1.2036x over previous
#include <cuda_runtime.h>
#include <cuda_bf16.h>
#include <math.h>

// ---------------------------------------------------------------------------
// Handwriting synthesis network (Graves attention, 3x LSTM-512, GMM head)
// B=64 T=800 U=100 V=80 H=512 KA=10 KO=20
// Persistent scans; attention decoupled from the critical path via split
// signal/wait barriers; coalesced transposed W_att; cp.async staging.
// ---------------------------------------------------------------------------

#define Bn   64
#define Tn   800
#define Un   100
#define Vn   80
#define Hn   512
#define KAn  10
#define Gn   2048          // 4*H
#define K1   595           // 3+V+H
#define K1P  608           // padded
#define FCK  1536          // 3*H
#define OUTC 121

// -------------------- f32x2 / async helpers ---------------------------------
__device__ __forceinline__ unsigned long long pack2(float x, float y)
{
    unsigned long long r;
    asm("mov.b64 %0, {%1, %2};" : "=l"(r) : "f"(x), "f"(y));
    return r;
}
__device__ __forceinline__ void fma2(unsigned long long& d,
                                     unsigned long long a, unsigned long long b)
{
    asm("fma.rn.f32x2 %0, %1, %2, %0;" : "+l"(d) : "l"(a), "l"(b));
}
__device__ __forceinline__ float2 unpk(unsigned long long v)
{
    float2 f;
    asm("mov.b64 {%0, %1}, %2;" : "=f"(f.x), "=f"(f.y) : "l"(v));
    return f;
}
__device__ __forceinline__ unsigned long long add2(unsigned long long a,
                                                   unsigned long long b)
{
    unsigned long long r;
    asm("add.rn.f32x2 %0, %1, %2;" : "=l"(r) : "l"(a), "l"(b));
    return r;
}
#define CP_ASYNC16(dst_u32, src_ptr) \
    asm volatile("cp.async.cg.shared.global [%0], [%1], 16;" \
                 :: "r"(dst_u32), "l"(src_ptr))
#define CP_COMMIT() asm volatile("cp.async.commit_group;")
#define CP_WAIT0()  asm volatile("cp.async.wait_group 0;" ::: "memory")

// -------------------- static device scratch --------------------------------
__device__ float g_h0[(size_t)Tn*Bn*Hn];
__device__ float g_h1[(size_t)Tn*Bn*Hn];
__device__ float g_h2[(size_t)Tn*Bn*Hn];
__device__ float g_w [(size_t)Tn*Bn*Vn];
__device__ float g_hT[2*Hn*Bn];            // transposed h, double buffered
__device__ float g_wT[2*Vn*Bn];            // transposed w, double buffered
__device__ float g_kap[Bn*KAn];
// packed weight layouts: [k][ht(64)][u(8)][g(4)]
__device__ float g_Whp0[(size_t)Hn*Gn];
__device__ float g_Whp1[(size_t)Hn*Gn];
__device__ float g_Whp2[(size_t)Hn*Gn];
__device__ float g_Wxp0[(size_t)96*Gn];
__device__ float g_WaT[512*32];            // W_att transposed [k][30->32]
__device__ float g_cat[(size_t)Tn*Bn*K1P];
__device__ float g_pre[(size_t)Tn*Bn*Gn];  // layout [n][unit(512)][gate(4)]
__device__ float g_fcraw[(size_t)Tn*Bn*OUTC];

// flag arrays: one 128B line per block flag
__device__ unsigned g_flagH[2*64*32];
__device__ unsigned g_flagW[2*32*32];

__device__ __forceinline__ float sigf(float x) { return 1.f/(1.f+expf(-x)); }

__device__ __forceinline__ void bar_signal(unsigned* fl, unsigned ep)
{
    __syncthreads();
    if (threadIdx.x == 0)
        asm volatile("st.release.gpu.u32 [%0], %1;" :: "l"(fl), "r"(ep) : "memory");
}
__device__ __forceinline__ void bar_wait_n(const unsigned* base, int n, unsigned ep)
{
    if (threadIdx.x < (unsigned)n) {
        const unsigned* f = base + threadIdx.x*32;
        unsigned v;
        do {
            asm volatile("ld.acquire.gpu.u32 %0, [%1];" : "=r"(v) : "l"(f) : "memory");
        } while (v < ep);
    }
    __syncthreads();
}

// -------------------- prep kernels ------------------------------------------
__global__ void k_prep_whh(const float* __restrict__ W, int layer)
{
    int idx = blockIdx.x * 256 + threadIdx.x;
    if (idx >= Hn*Gn) return;
    int g  = idx & 3;
    int u  = (idx >> 2) & 7;
    int ht = (idx >> 5) & 63;
    int k  = idx >> 11;
    float v = W[(size_t)(g*Hn + ht*8 + u)*Hn + k];
    if (layer == 0)      g_Whp0[idx] = v;
    else if (layer == 1) g_Whp1[idx] = v;
    else                 g_Whp2[idx] = v;
}

__global__ void k_prep_wx0(const float* __restrict__ Wih0,
                           const float* __restrict__ W_att)
{
    int idx = blockIdx.x * 256 + threadIdx.x;
    if (idx < 2*64*32) g_flagH[idx] = 0;
    if (idx < 2*32*32) g_flagW[idx] = 0;
    if (idx < 512*32) {
        int k = idx >> 5, r = idx & 31;
        g_WaT[idx] = (r < 30) ? W_att[(size_t)r*Hn + k] : 0.f;
    }
    if (idx >= 96*Gn) return;
    int g  = idx & 3;
    int u  = (idx >> 2) & 7;
    int ht = (idx >> 5) & 63;
    int k  = idx >> 11;
    g_Wxp0[idx] = (k < 83) ? Wih0[(size_t)(g*Hn + ht*8 + u)*83 + k] : 0.f;
}

// -------------------- persistent scan shapes ---------------------------------
// grid 128 = (bt 0..1)*64 + (ht 0..63). block 256 threads.
// thread: bl = tid&31 (batch), q = (tid>>5)&3 (u-pair), s = tid>>7 (k-half).
#define WS_F   (512*32)
#define WS0_F  (96*32)
#define HS_F   (512*32)
#define XS_F   (96*32)
#define RED_F  (128*8)
#define ATT_F  384

__device__ __forceinline__ void attn_step(
    int t, int b, const float* __restrict__ b_att,
    const int* __restrict__ chars, const float* __restrict__ cmask, float* sc)
{
    float* red = sc;          // 256
    float* abk = sc + 256;    // 30
    float* wsh = sc + 288;    // 80
    const int tid = threadIdx.x;
    const float* h0 = &g_h0[((size_t)t*Bn + b)*Hn];

    int r = tid & 31, q = tid >> 5;           // q 0..7, chunks of 64 k
    float s = 0.f;
    {
        const float* wa = &g_WaT[q*64*32 + r];   // coalesced across lanes
        const float* hh = &h0[q*64];             // broadcast across lanes
        #pragma unroll 16
        for (int k = 0; k < 64; k++)
            s += __ldg(&hh[k]) * wa[k*32];
    }
    red[tid] = s;
    __syncthreads();
    if (tid < 30) {
        float tot = b_att[tid];
        #pragma unroll
        for (int q2 = 0; q2 < 8; q2++) tot += red[tid + 32*q2];
        abk[tid] = expf(tot);
    }
    __syncthreads();
    if (tid < 10) {
        float kn = abk[20 + tid] * 0.05f + g_kap[b*KAn + tid];
        g_kap[b*KAn + tid] = kn;
        abk[20 + tid] = kn;
    }
    if (tid >= 32 && tid < 112) wsh[tid - 32] = 0.f;
    __syncthreads();
    if (tid < 100) {
        float uu = (float)tid;
        float phi = 0.f;
        #pragma unroll
        for (int a = 0; a < 10; a++) {
            float d = abk[20 + a] - uu;
            phi += abk[a] * expf(-abk[10 + a] * d * d);
        }
        float m = cmask[(size_t)b*Un + tid];
        phi *= m * m;
        atomicAdd(&wsh[chars[(size_t)b*Un + tid]], phi);
    }
    __syncthreads();
    if (tid < 80) {
        float v = wsh[tid];
        g_w[((size_t)t*Bn + b)*Vn + tid] = v;
        g_wT[(t&1)*Vn*Bn + tid*Bn + b] = v;       // transposed copy
    }
}

__global__ __launch_bounds__(256, 1)
void k_scan0(const float* __restrict__ strokes, const float* __restrict__ b0v,
             const float* __restrict__ b_att,
             const int* __restrict__ chars, const float* __restrict__ cmask)
{
    extern __shared__ float sm[];
    float* ws   = sm;                               // [k][32]
    float* ws0  = sm + WS_F;                        // [k][32]
    float* hs   = sm + WS_F + WS0_F;                // [k][32]
    float* xs   = sm + WS_F + WS0_F + HS_F;         // [k][32]
    float* red  = sm + WS_F + WS0_F + HS_F + XS_F;  // [128][8]
    float* atts = red + RED_F;                      // 384

    const int bt  = blockIdx.x >> 6;
    const int ht  = blockIdx.x & 63;
    const int tid = threadIdx.x;
    const int bl  = tid & 31;
    const int q   = (tid >> 5) & 3;
    const int s   = tid >> 7;
    const int b   = bt*32 + bl;

    unsigned* myH = &g_flagH[(bt*64 + ht)*32];
    unsigned* grpH = &g_flagH[bt*64*32];
    unsigned* grpW = &g_flagW[bt*32*32];

    for (int idx = tid; idx < WS_F; idx += 256)
        ws[idx] = g_Whp0[(size_t)(idx >> 5)*Gn + ht*32 + (idx & 31)];
    for (int idx = tid; idx < WS0_F; idx += 256)
        ws0[idx] = g_Wxp0[(size_t)(idx >> 5)*Gn + ht*32 + (idx & 31)];
    // zero pad rows of xs once (k in [83,96))
    for (int idx = 83*32 + tid; idx < 96*32; idx += 256)
        xs[idx] = 0.f;

    const int u0 = ht*8 + q*2, u1 = u0 + 1;
    unsigned long long b0_01 = 0, b0_23 = 0, b1_01 = 0, b1_23 = 0;
    if (s == 0) {
        b0_01 = pack2(b0v[u0], b0v[Hn + u0]);
        b0_23 = pack2(b0v[2*Hn + u0], b0v[3*Hn + u0]);
        b1_01 = pack2(b0v[u1], b0v[Hn + u1]);
        b1_23 = pack2(b0v[2*Hn + u1], b0v[3*Hn + u1]);
    }
    if (ht < 32 && tid < KAn) g_kap[(bt*32 + ht)*KAn + tid] = 0.f;
    float c0 = 0.f, c1 = 0.f;
    __syncthreads();

    const unsigned hs_base = (unsigned)__cvta_generic_to_shared(hs);

    for (int t = 0; t < Tn; t++) {
        // ---- stage h tile [512][32] via cp.async (L2-direct)
        if (t > 0) {
            const float* src = &g_hT[((t-1)&1)*Hn*Bn + bt*32];
            #pragma unroll
            for (int j = 0; j < 16; j++) {
                int idx = tid*4 + j*1024;
                int k = idx >> 5, cc = idx & 31;
                CP_ASYNC16(hs_base + idx*4, &src[k*64 + cc]);
            }
            CP_COMMIT();
            CP_WAIT0();
        }
        __syncthreads();

        unsigned long long a0_01 = b0_01, a0_23 = b0_23;
        unsigned long long a1_01 = b1_01, a1_23 = b1_23;

        // ---- recurrent part first (independent of w[t-1])
        if (t > 0) {
            const int k0 = s*256;
            #pragma unroll 8
            for (int k = k0; k < k0 + 256; k++) {
                ulonglong2 w0 = *(const ulonglong2*)&ws[k*32 + q*8];
                ulonglong2 w1 = *(const ulonglong2*)&ws[k*32 + q*8 + 4];
                float x = hs[k*32 + bl];
                unsigned long long xx = pack2(x, x);
                fma2(a0_01, xx, w0.x); fma2(a0_23, xx, w0.y);
                fma2(a1_01, xx, w1.x); fma2(a1_23, xx, w1.y);
            }
            // w[t-1] was produced overlapped with the compute above
            bar_wait_n(grpW, 32, (unsigned)t);
        }

        // ---- stage x rows [0,83): strokes(3) | w_prev(80)
        for (int idx = tid; idx < 83*32; idx += 256) {
            int k = idx >> 5, cc = idx & 31;
            int b2 = bt*32 + cc;
            float v = 0.f;
            if (k < 3)       v = strokes[((size_t)b2*Tn + t)*3 + k];
            else if (t > 0)  v = __ldcg(&g_wT[((t-1)&1)*Vn*Bn + (k-3)*Bn + b2]);
            xs[idx] = v;
        }
        __syncthreads();

        // ---- x part: k in [s*48, s*48+48)
        {
            const int k0 = s*48;
            #pragma unroll 8
            for (int k = k0; k < k0 + 48; k++) {
                ulonglong2 w0 = *(const ulonglong2*)&ws0[k*32 + q*8];
                ulonglong2 w1 = *(const ulonglong2*)&ws0[k*32 + q*8 + 4];
                float x = xs[k*32 + bl];
                unsigned long long xx = pack2(x, x);
                fma2(a0_01, xx, w0.x); fma2(a0_23, xx, w0.y);
                fma2(a1_01, xx, w1.x); fma2(a1_23, xx, w1.y);
            }
        }
        // ---- reduce the two k-halves
        if (s == 1) {
            float* rp = &red[(tid - 128)*8];
            *(unsigned long long*)(rp+0) = a0_01;
            *(unsigned long long*)(rp+2) = a0_23;
            *(unsigned long long*)(rp+4) = a1_01;
            *(unsigned long long*)(rp+6) = a1_23;
        }
        __syncthreads();
        if (s == 0) {
            const float* rp = &red[tid*8];
            a0_01 = add2(a0_01, *(const unsigned long long*)(rp+0));
            a0_23 = add2(a0_23, *(const unsigned long long*)(rp+2));
            a1_01 = add2(a1_01, *(const unsigned long long*)(rp+4));
            a1_23 = add2(a1_23, *(const unsigned long long*)(rp+6));

            float2 g01 = unpk(a0_01), g23 = unpk(a0_23);
            float ig = sigf(g01.x), fg = sigf(g01.y);
            float gg = tanhf(g23.x), og = sigf(g23.y);
            c0 = fg*c0 + ig*gg;
            float h0v = og * tanhf(c0);
            g01 = unpk(a1_01); g23 = unpk(a1_23);
            ig = sigf(g01.x); fg = sigf(g01.y);
            gg = tanhf(g23.x); og = sigf(g23.y);
            c1 = fg*c1 + ig*gg;
            float h1v = og * tanhf(c1);

            g_h0[((size_t)t*Bn + b)*Hn + u0] = h0v;
            g_h0[((size_t)t*Bn + b)*Hn + u1] = h1v;
            float* dst = &g_hT[(t&1)*Hn*Bn];
            dst[u0*64 + b] = h0v;
            dst[u1*64 + b] = h1v;
        }
        bar_signal(myH, (unsigned)(t+1));
        bar_wait_n(grpH, 64, (unsigned)(t+1));   // h0[t] complete everywhere

        if (ht < 32) {
            attn_step(t, bt*32 + ht, b_att, chars, cmask, atts);
            bar_signal(&g_flagW[(bt*32 + ht)*32], (unsigned)(t+1));
        }
        // other blocks run ahead into step t+1's recurrent compute
    }
}

// -------------------- persistent scan: layers 1/2 ---------------------------
__global__ __launch_bounds__(256, 1)
void k_scan12(int layer, unsigned epbase)
{
    extern __shared__ float sm[];
    float* ws  = sm;                 // [k][32]
    float* hs  = sm + WS_F;          // [k][32]
    float* red = sm + WS_F + HS_F;   // [128][8]

    const float* whp  = (layer == 1) ? g_Whp1 : g_Whp2;
    float*       hseq = (layer == 1) ? g_h1   : g_h2;

    const int bt  = blockIdx.x >> 6;
    const int ht  = blockIdx.x & 63;
    const int tid = threadIdx.x;
    const int bl  = tid & 31;
    const int q   = (tid >> 5) & 3;
    const int s   = tid >> 7;
    const int b   = bt*32 + bl;
    const int u0  = ht*8 + q*2, u1 = u0 + 1;

    unsigned* myH = &g_flagH[(bt*64 + ht)*32];
    unsigned* grpH = &g_flagH[bt*64*32];

    for (int idx = tid; idx < WS_F; idx += 256)
        ws[idx] = whp[(size_t)(idx >> 5)*Gn + ht*32 + (idx & 31)];
    float c0 = 0.f, c1 = 0.f;
    __syncthreads();

    const unsigned hs_base = (unsigned)__cvta_generic_to_shared(hs);

    for (int t = 0; t < Tn; t++) {
        unsigned long long a0_01 = 0, a0_23 = 0, a1_01 = 0, a1_23 = 0;
        if (s == 0) {
            const float* pp = &g_pre[(((size_t)t*Bn + b)*Hn)*4];
            float4 p0 = *(const float4*)&pp[u0*4];
            float4 p1 = *(const float4*)&pp[u1*4];
            a0_01 = pack2(p0.x, p0.y); a0_23 = pack2(p0.z, p0.w);
            a1_01 = pack2(p1.x, p1.y); a1_23 = pack2(p1.z, p1.w);
        }

        if (t > 0) {
            const float* src = &g_hT[((t-1)&1)*Hn*Bn + bt*32];
            #pragma unroll
            for (int j = 0; j < 16; j++) {
                int idx = tid*4 + j*1024;
                int k = idx >> 5, cc = idx & 31;
                CP_ASYNC16(hs_base + idx*4, &src[k*64 + cc]);
            }
            CP_COMMIT();
            CP_WAIT0();
        }
        __syncthreads();

        if (t > 0) {
            const int k0 = s*256;
            #pragma unroll 8
            for (int k = k0; k < k0 + 256; k++) {
                ulonglong2 w0 = *(const ulonglong2*)&ws[k*32 + q*8];
                ulonglong2 w1 = *(const ulonglong2*)&ws[k*32 + q*8 + 4];
                float x = hs[k*32 + bl];
                unsigned long long xx = pack2(x, x);
                fma2(a0_01, xx, w0.x); fma2(a0_23, xx, w0.y);
                fma2(a1_01, xx, w1.x); fma2(a1_23, xx, w1.y);
            }
        }
        if (s == 1) {
            float* rp = &red[(tid - 128)*8];
            *(unsigned long long*)(rp+0) = a0_01;
            *(unsigned long long*)(rp+2) = a0_23;
            *(unsigned long long*)(rp+4) = a1_01;
            *(unsigned long long*)(rp+6) = a1_23;
        }
        __syncthreads();
        if (s == 0) {
            const float* rp = &red[tid*8];
            a0_01 = add2(a0_01, *(const unsigned long long*)(rp+0));
            a0_23 = add2(a0_23, *(const unsigned long long*)(rp+2));
            a1_01 = add2(a1_01, *(const unsigned long long*)(rp+4));
            a1_23 = add2(a1_23, *(const unsigned long long*)(rp+6));

            float2 g01 = unpk(a0_01), g23 = unpk(a0_23);
            float ig = sigf(g01.x), fg = sigf(g01.y);
            float gg = tanhf(g23.x), og = sigf(g23.y);
            c0 = fg*c0 + ig*gg;
            float h0v = og * tanhf(c0);
            g01 = unpk(a1_01); g23 = unpk(a1_23);
            ig = sigf(g01.x); fg = sigf(g01.y);
            gg = tanhf(g23.x); og = sigf(g23.y);
            c1 = fg*c1 + ig*gg;
            float h1v = og * tanhf(c1);

            hseq[((size_t)t*Bn + b)*Hn + u0] = h0v;
            hseq[((size_t)t*Bn + b)*Hn + u1] = h1v;
            float* dst = &g_hT[(t&1)*Hn*Bn];
            dst[u0*64 + b] = h0v;
            dst[u1*64 + b] = h1v;
        }
        bar_signal(myH, epbase + (unsigned)(t+1));
        bar_wait_n(grpH, 64, epbase + (unsigned)(t+1));
    }
}

// -------------------- cat fill ------------------------------------------------
__global__ void k_fill_cat0(const float* __restrict__ strokes)
{
    size_t idx = (size_t)blockIdx.x * 256 + threadIdx.x;  // over T*B*608
    if (idx >= (size_t)Tn*Bn*K1P) return;
    int k = (int)(idx % K1P);
    size_t n = idx / K1P;
    int t = (int)(n >> 6), b = (int)(n & 63);
    float v = 0.f;
    if (k < 3)        v = strokes[((size_t)b*Tn + t)*3 + k];
    else if (k < 83)  v = g_w[n*Vn + (k-3)];
    else if (k < 595) v = g_h0[n*Hn + (k-83)];
    g_cat[idx] = v;
}

__global__ void k_fill_cat_h1()
{
    size_t idx = (size_t)blockIdx.x * 256 + threadIdx.x;  // over T*B*512
    if (idx >= (size_t)Tn*Bn*Hn) return;
    size_t n = idx >> 9;
    int k = (int)(idx & 511);
    g_cat[n*K1P + 83 + k] = g_h1[idx];
}

// -------------------- batched GEMM: pre = cat @ Wih^T + b -------------------
// output packed [n][unit(512)][gate(4)]
__global__ __launch_bounds__(256, 2)
void k_gemm_pre(const float* __restrict__ Wih, const float* __restrict__ bias)
{
    const int n0 = blockIdx.x * 64;
    const int j0 = blockIdx.y * 64;
    const int tid = threadIdx.x;
    const int tm = tid >> 4, tn = tid & 15;
    const int mload = tid >> 2;
    const int kq = (tid & 3) * 4;

    __shared__ float As[16][68];
    __shared__ float Bs[16][68];

    unsigned long long acc2[4][2];
    #pragma unroll
    for (int i = 0; i < 4; i++) { acc2[i][0] = 0ull; acc2[i][1] = 0ull; }

    for (int k0 = 0; k0 < K1P; k0 += 16) {
        float4 av = *(const float4*)&g_cat[(size_t)(n0+mload)*K1P + k0 + kq];
        As[kq+0][mload] = av.x; As[kq+1][mload] = av.y;
        As[kq+2][mload] = av.z; As[kq+3][mload] = av.w;

        const float* bptr = &Wih[(size_t)(j0+mload)*K1 + k0 + kq];
        #pragma unroll
        for (int i = 0; i < 4; i++) {
            int k = k0 + kq + i;
            Bs[kq+i][mload] = (k < K1) ? bptr[i] : 0.f;
        }
        __syncthreads();
        #pragma unroll
        for (int kk = 0; kk < 16; kk++) {
            float4 a4 = *(const float4*)&As[kk][tm*4];
            ulonglong2 b2 = *(const ulonglong2*)&Bs[kk][tn*4];
            unsigned long long ax;
            ax = pack2(a4.x, a4.x); fma2(acc2[0][0], ax, b2.x); fma2(acc2[0][1], ax, b2.y);
            ax = pack2(a4.y, a4.y); fma2(acc2[1][0], ax, b2.x); fma2(acc2[1][1], ax, b2.y);
            ax = pack2(a4.z, a4.z); fma2(acc2[2][0], ax, b2.x); fma2(acc2[2][1], ax, b2.y);
            ax = pack2(a4.w, a4.w); fma2(acc2[3][0], ax, b2.x); fma2(acc2[3][1], ax, b2.y);
        }
        __syncthreads();
    }

    const int g = j0 >> 9;   // gate index
    #pragma unroll
    for (int i = 0; i < 4; i++) {
        int n = n0 + tm*4 + i;
        float2 c01 = unpk(acc2[i][0]);
        float2 c23 = unpk(acc2[i][1]);
        float cv[4] = {c01.x, c01.y, c23.x, c23.y};
        #pragma unroll
        for (int jj = 0; jj < 4; jj++) {
            int j = j0 + tn*4 + jj;
            int unit = j & 511;
            g_pre[((size_t)n*Hn + unit)*4 + g] = cv[jj] + bias[j];
        }
    }
}

// -------------------- FC GEMM: fcraw = [h0|h1|h2] @ Wfc^T + b ---------------
__global__ __launch_bounds__(256, 2)
void k_gemm_fc(const float* __restrict__ Wfc, const float* __restrict__ bfc)
{
    const int n0 = blockIdx.x * 64;
    const int j0 = blockIdx.y * 64;
    const int tid = threadIdx.x;
    const int tm = tid >> 4, tn = tid & 15;
    const int mload = tid >> 2;
    const int kq = (tid & 3) * 4;

    __shared__ float As[16][68];
    __shared__ float Bs[16][68];

    unsigned long long acc2[4][2];
    #pragma unroll
    for (int i = 0; i < 4; i++) { acc2[i][0] = 0ull; acc2[i][1] = 0ull; }

    for (int k0 = 0; k0 < FCK; k0 += 16) {
        const float* hsrc = (k0 < 512) ? g_h0 : (k0 < 1024) ? g_h1 : g_h2;
        int krel = (k0 & 511) + kq;
        float4 av = *(const float4*)&hsrc[(size_t)(n0+mload)*Hn + krel];
        As[kq+0][mload] = av.x; As[kq+1][mload] = av.y;
        As[kq+2][mload] = av.z; As[kq+3][mload] = av.w;

        int rowj = j0 + mload;
        if (rowj < OUTC) {
            const float* bptr = &Wfc[(size_t)rowj*FCK + k0 + kq];
            Bs[kq+0][mload] = bptr[0]; Bs[kq+1][mload] = bptr[1];
            Bs[kq+2][mload] = bptr[2]; Bs[kq+3][mload] = bptr[3];
        } else {
            Bs[kq+0][mload] = 0.f; Bs[kq+1][mload] = 0.f;
            Bs[kq+2][mload] = 0.f; Bs[kq+3][mload] = 0.f;
        }
        __syncthreads();
        #pragma unroll
        for (int kk = 0; kk < 16; kk++) {
            float4 a4 = *(const float4*)&As[kk][tm*4];
            ulonglong2 b2 = *(const ulonglong2*)&Bs[kk][tn*4];
            unsigned long long ax;
            ax = pack2(a4.x, a4.x); fma2(acc2[0][0], ax, b2.x); fma2(acc2[0][1], ax, b2.y);
            ax = pack2(a4.y, a4.y); fma2(acc2[1][0], ax, b2.x); fma2(acc2[1][1], ax, b2.y);
            ax = pack2(a4.z, a4.z); fma2(acc2[2][0], ax, b2.x); fma2(acc2[2][1], ax, b2.y);
            ax = pack2(a4.w, a4.w); fma2(acc2[3][0], ax, b2.x); fma2(acc2[3][1], ax, b2.y);
        }
        __syncthreads();
    }

    #pragma unroll
    for (int i = 0; i < 4; i++) {
        int n = n0 + tm*4 + i;
        float2 c01 = unpk(acc2[i][0]);
        float2 c23 = unpk(acc2[i][1]);
        float cv[4] = {c01.x, c01.y, c23.x, c23.y};
        #pragma unroll
        for (int jj = 0; jj < 4; jj++) {
            int jcol = j0 + tn*4 + jj;
            if (jcol < OUTC)
                g_fcraw[(size_t)n*OUTC + jcol] = cv[jj] + bfc[jcol];
        }
    }
}

// -------------------- epilogue ------------------------------------------------
__global__ void k_epilogue(float* __restrict__ out)
{
    int n = blockIdx.x * 128 + threadIdx.x;
    if (n >= Tn*Bn) return;
    const float* r = &g_fcraw[(size_t)n*OUTC];
    int t = n >> 6, b = n & 63;
    float* o = &out[((size_t)b*Tn + t)*OUTC];

    float mx = -1e30f;
    #pragma unroll
    for (int k = 0; k < 20; k++) mx = fmaxf(mx, r[80 + k]);
    float se = 0.f;
    #pragma unroll
    for (int k = 0; k < 20; k++) se += expf(r[80 + k] - mx);
    float lse = mx + logf(se);
    #pragma unroll
    for (int k = 0; k < 20; k++) o[k] = r[80 + k] - lse;          // log_pi
    #pragma unroll
    for (int k = 0; k < 40; k++) o[20 + k] = r[k];                // mu
    #pragma unroll
    for (int k = 0; k < 40; k++) o[60 + k] = r[40 + k];           // log_sigma
    #pragma unroll
    for (int k = 0; k < 20; k++) o[100 + k] = tanhf(r[100 + k]);  // rho
    o[120] = 1.f / (1.f + expf(r[120]));                          // sigmoid(-eos)
}

// -------------------- host launch ---------------------------------------------
extern "C" void kernel_launch(void* const* d_in, const int* in_sizes, int n_in,
                              void* d_out, int out_size)
{
    const int*   chars   = (const int*)  d_in[0];
    const float* cmask   = (const float*)d_in[1];
    const float* strokes = (const float*)d_in[2];
    // d_in[3] strokes_mask unused by reference
    const float* W_ih0   = (const float*)d_in[4];
    const float* W_hh0   = (const float*)d_in[5];
    const float* b0      = (const float*)d_in[6];
    const float* W_att   = (const float*)d_in[7];
    const float* b_att   = (const float*)d_in[8];
    const float* W_ih1   = (const float*)d_in[9];
    const float* W_hh1   = (const float*)d_in[10];
    const float* b1      = (const float*)d_in[11];
    const float* W_ih2   = (const float*)d_in[12];
    const float* W_hh2   = (const float*)d_in[13];
    const float* b2      = (const float*)d_in[14];
    const float* W_fc    = (const float*)d_in[15];
    const float* b_fc    = (const float*)d_in[16];
    float* out = (float*)d_out;

    const int SM0  = (WS_F + WS0_F + HS_F + XS_F + RED_F + ATT_F) * 4;  // 161,280 B
    const int SM12 = (WS_F + HS_F + RED_F) * 4;                          // 135,168 B
    cudaFuncSetAttribute(k_scan0,  cudaFuncAttributeMaxDynamicSharedMemorySize, SM0);
    cudaFuncSetAttribute(k_scan12, cudaFuncAttributeMaxDynamicSharedMemorySize, SM12);

    // preps (k_scan0 remains early for ncu capture slot alignment)
    k_prep_whh<<<(Hn*Gn + 255)/256, 256>>>(W_hh0, 0);
    k_prep_wx0<<<(96*Gn + 255)/256, 256>>>(W_ih0, W_att);  // flags + WaT too
    k_prep_whh<<<(Hn*Gn + 255)/256, 256>>>(W_hh1, 1);

    // layer 0 scan (lstm0 + attention), persistent
    k_scan0<<<128, 256, SM0>>>(strokes, b0, b_att, chars, cmask);

    k_prep_whh<<<(Hn*Gn + 255)/256, 256>>>(W_hh2, 2);

    // layer 1
    {
        size_t tot = (size_t)Tn*Bn*K1P;
        k_fill_cat0<<<(unsigned)((tot + 255)/256), 256>>>(strokes);
    }
    k_gemm_pre<<<dim3(Tn*Bn/64, Gn/64), 256>>>(W_ih1, b1);
    k_scan12<<<128, 256, SM12>>>(1, 800u);

    // layer 2
    {
        size_t tot = (size_t)Tn*Bn*Hn;
        k_fill_cat_h1<<<(unsigned)((tot + 255)/256), 256>>>();
    }
    k_gemm_pre<<<dim3(Tn*Bn/64, Gn/64), 256>>>(W_ih2, b2);
    k_scan12<<<128, 256, SM12>>>(2, 1600u);

    // head
    k_gemm_fc<<<dim3(Tn*Bn/64, 2), 256>>>(W_fc, b_fc);
    k_epilogue<<<(Tn*Bn + 127)/128, 128>>>(out);
}